// round 9
// baseline (speedup 1.0000x reference)
#include <cuda_runtime.h>
#include <cuda/atomic>
#include <cstdint>

#define TSTEPS 300
#define HIDN   512
#define EMBD   300
#define G4     2048      // 4*HIDN
#define NCTA   32
#define TPB    512
#define SPIN_GUARD (1 << 16)

typedef unsigned long long u64;

// ---------------- scratch (static __device__, no allocs) ----------------
__device__ __align__(16) float g_pre[TSTEPS * G4]; // input-side gates (+biases)
__device__ __align__(16) u64   g_hw[2][HIDN];      // tagged hidden words: (tag<<32)|bits
                                                   // tag s = "h after s steps"

using dev_atomic_u64 = cuda::atomic_ref<u64, cuda::thread_scope_device>;

__device__ __forceinline__ u64 pack_h(float v, unsigned tag) {
    return ((u64)tag << 32) | (u64)__float_as_uint(v);
}

__device__ __forceinline__ float sigm(float x) { return 1.f / (1.f + __expf(-x)); }
__device__ __forceinline__ float tanh_f(float x) {
    // overflow-safe: tanh(x) = sign(x) * (1 - 2/(exp(2|x|)+1))
    float e = __expf(2.f * fabsf(x));
    float r = 1.f - 2.f / (e + 1.f);
    return copysignf(r, x);
}

// ================= Phase 1: pre[t][row] = W_ih @ emb[x[t]] + b_ih + b_hh ==========
// grid (128, 19), block 256.  Block covers 16 rows x 16 timesteps; K=300 loop.
__global__ void pre_kernel(const int* __restrict__ x,
                           const float* __restrict__ emb,
                           const float* __restrict__ W_ih,
                           const float* __restrict__ b_ih,
                           const float* __restrict__ b_hh,
                           const float* __restrict__ h0)
{
    __shared__ float E[16][301];   // stride 301 -> conflict-free column reads
    const int tB = blockIdx.y * 16;
    const int rB = blockIdx.x * 16;

    for (int idx = threadIdx.x; idx < 16 * EMBD; idx += 256) {
        int tt = idx / EMBD, k = idx % EMBD;
        int t = tB + tt;
        E[tt][k] = (t < TSTEPS) ? emb[(size_t)x[t] * EMBD + k] : 0.f;
    }
    __syncthreads();

    const int t_local = threadIdx.x & 15;
    const int r_local = threadIdx.x >> 4;
    const int r = rB + r_local;
    const int t = tB + t_local;

    const float* wr = W_ih + (size_t)r * EMBD;
    float a0 = 0.f, a1 = 0.f, a2 = 0.f, a3 = 0.f;
    #pragma unroll 4
    for (int k = 0; k < EMBD; k += 4) {
        a0 = fmaf(wr[k + 0], E[t_local][k + 0], a0);
        a1 = fmaf(wr[k + 1], E[t_local][k + 1], a1);
        a2 = fmaf(wr[k + 2], E[t_local][k + 2], a2);
        a3 = fmaf(wr[k + 3], E[t_local][k + 3], a3);
    }
    if (t < TSTEPS)
        g_pre[(size_t)t * G4 + r] = (a0 + a1) + (a2 + a3) + b_ih[r] + b_hh[r];

    // block (0,0): seed h words with tag 0 and poison the other buffer's tags
    if (blockIdx.x == 0 && blockIdx.y == 0) {
        for (int i = threadIdx.x; i < HIDN; i += 256) {
            dev_atomic_u64 a0ref(g_hw[0][i]);
            dev_atomic_u64 a1ref(g_hw[1][i]);
            a0ref.store(pack_h(h0[i], 0u), cuda::memory_order_relaxed);
            a1ref.store(((u64)0xFFFFFFFFu << 32), cuda::memory_order_relaxed);
        }
    }
}

// ================= Phase 2: persistent recurrence, pure dataflow =================
// 32 CTAs x 512 threads.  CTA c owns hidden units [16c,16c+16) -> 64 gate rows
// (row q: gate = q>>4, local unit = q&15).
// Warp-pair p (warps 2p,2p+1) handles all 64 rows x cols [64p, 64p+64).
// Thread (pair p, half, lane): row q = half*32+lane; weights W_hh[grow(q)][64p..]
// in 64 registers.  Each lane polls TWO tagged L2 h-words (units 64p+lane,
// 64p+32+lane); the 64 h values are shfl-broadcast during the FMA loop.
// Partials / activations flow through tagged smem words, PARITY DOUBLE-BUFFERED
// (the R8 race: a pair warp only waits on owners of CTAs 4p..4p+3, so it can run
// one step ahead of its own CTA's reducers; two steps ahead is provably blocked
// through the h-tag chain, so two parity slots suffice).
// NO __syncthreads, NO fences anywhere in the step loop.
__global__ void __launch_bounds__(TPB, 1)
lstm_persist(const float* __restrict__ W_hh,
             const float* __restrict__ c0,
             const float* __restrict__ fc_w,
             const float* __restrict__ fc_b,
             float* __restrict__ out)
{
    const int c    = blockIdx.x;
    const int t    = threadIdx.x;
    const int warp = t >> 5;
    const int lane = t & 31;
    const int pair = warp >> 1;            // 0..7  (column chunk)
    const int half = warp & 1;             // 0/1
    const int q    = (half << 5) | lane;   // row in CTA, 0..63
    const int grow = (q >> 4) * HIDN + (c << 4) + (q & 15);  // global gate row

    const int unitA = (pair << 6) + lane;        // first polled unit
    const int unitB = (pair << 6) + 32 + lane;   // second polled unit

    __shared__ volatile u64 s_part[2][8][64];  // [parity][chunk][row] tagged partials
    __shared__ volatile u64 s_act[2][64];      // [parity][row] tagged activated gates
    __shared__ float red[16];

    // ---- init smem tags (both parity slots), once ----
    for (int i = t; i < 2 * 8 * 64; i += TPB)
        s_part[i >> 9][(i >> 6) & 7][i & 63] = ((u64)0xFFFFFFFFu << 32);
    if (t < 128) s_act[t >> 6][t & 63] = ((u64)0xFFFFFFFFu << 32);
    __syncthreads();                       // once, outside the step loop

    // ---- load W_hh slice into registers (kept for all 300 steps) ----
    float w[64];
    {
        const float4* wrow =
            reinterpret_cast<const float4*>(W_hh + (size_t)grow * HIDN + (pair << 6));
        #pragma unroll
        for (int i = 0; i < 16; ++i) {
            float4 v = wrow[i];
            w[4 * i + 0] = v.x; w[4 * i + 1] = v.y;
            w[4 * i + 2] = v.z; w[4 * i + 3] = v.w;
        }
    }

    float cv = 0.f, hv = 0.f;              // state for the 16 owner threads
    if (t < 16) cv = c0[(c << 4) + t];

    for (int step = 0; step < TSTEPS; ++step) {
        const int buf = step & 1;          // h-buffer parity AND smem parity
        const unsigned utag = (unsigned)step;

        // prefetch input-side gate value (reducers need it; in flight early)
        float prev = 0.f;
        if (t < 64) prev = __ldg(&g_pre[(size_t)step * G4 + grow]);

        // ---- poll the two tagged L2 words until both carry tag == step ----
        float vA, vB;
        {
            dev_atomic_u64 ra(g_hw[buf][unitA]);
            dev_atomic_u64 rb(g_hw[buf][unitB]);
            u64 a, b;
            int guard = 0;
            do {
                a = ra.load(cuda::memory_order_relaxed);
                b = rb.load(cuda::memory_order_relaxed);
            } while (((unsigned)(a >> 32) != utag || (unsigned)(b >> 32) != utag) &&
                     ++guard < SPIN_GUARD);
            vA = __uint_as_float((unsigned)a);
            vB = __uint_as_float((unsigned)b);
        }

        // ---- 64-MAC dot via shfl broadcast (no smem for h) ----
        float a0 = 0.f, a1 = 0.f, a2 = 0.f, a3 = 0.f;
        #pragma unroll
        for (int k = 0; k < 32; k += 4) {
            a0 = fmaf(w[k + 0], __shfl_sync(0xffffffffu, vA, k + 0), a0);
            a1 = fmaf(w[k + 1], __shfl_sync(0xffffffffu, vA, k + 1), a1);
            a2 = fmaf(w[k + 2], __shfl_sync(0xffffffffu, vA, k + 2), a2);
            a3 = fmaf(w[k + 3], __shfl_sync(0xffffffffu, vA, k + 3), a3);
        }
        #pragma unroll
        for (int k = 0; k < 32; k += 4) {
            a0 = fmaf(w[32 + k + 0], __shfl_sync(0xffffffffu, vB, k + 0), a0);
            a1 = fmaf(w[32 + k + 1], __shfl_sync(0xffffffffu, vB, k + 1), a1);
            a2 = fmaf(w[32 + k + 2], __shfl_sync(0xffffffffu, vB, k + 2), a2);
            a3 = fmaf(w[32 + k + 3], __shfl_sync(0xffffffffu, vB, k + 3), a3);
        }
        float part = (a0 + a1) + (a2 + a3);

        // ---- publish tagged partial into this step's parity slot ----
        s_part[buf][pair][q] = pack_h(part, utag);

        // ---- reducers (t<64): gather 8 partials, add pre, apply activation ----
        if (t < 64) {
            float ps[8];
            {
                int guard = 0;
                unsigned done = 0;
                u64 wv[8];
                do {
                    #pragma unroll
                    for (int s2 = 0; s2 < 8; ++s2)
                        if (!(done & (1u << s2))) {
                            wv[s2] = s_part[buf][s2][t];
                            if ((unsigned)(wv[s2] >> 32) == utag) done |= (1u << s2);
                        }
                } while (done != 0xFFu && ++guard < SPIN_GUARD);
                #pragma unroll
                for (int s2 = 0; s2 < 8; ++s2)
                    ps[s2] = __uint_as_float((unsigned)wv[s2]);
            }
            float gsum = (((ps[0] + ps[1]) + (ps[2] + ps[3])) +
                          ((ps[4] + ps[5]) + (ps[6] + ps[7]))) + prev;
            // gate: rows 0..15 i(sigm), 16..31 f(sigm), 32..47 g(tanh), 48..63 o(sigm)
            float act = (t < 32) ? sigm(gsum)
                                 : ((t < 48) ? tanh_f(gsum) : sigm(gsum));
            s_act[buf][t] = pack_h(act, utag);
        }

        // ---- owners (t<16): combine 4 activated gates, update state, publish ----
        if (t < 16) {
            u64 wi, wf, wg, wo;
            int guard = 0;
            do {
                wi = s_act[buf][t];
                wf = s_act[buf][16 + t];
                wg = s_act[buf][32 + t];
                wo = s_act[buf][48 + t];
            } while (((unsigned)(wi >> 32) != utag || (unsigned)(wf >> 32) != utag ||
                      (unsigned)(wg >> 32) != utag || (unsigned)(wo >> 32) != utag) &&
                     ++guard < SPIN_GUARD);
            float i_ = __uint_as_float((unsigned)wi);
            float f_ = __uint_as_float((unsigned)wf);
            float g_ = __uint_as_float((unsigned)wg);
            float o_ = __uint_as_float((unsigned)wo);
            float cn = fmaf(f_, cv, i_ * g_);
            cv = cn;
            hv = o_ * tanh_f(cn);
            dev_atomic_u64 hdst(g_hw[buf ^ 1][(c << 4) + t]);
            hdst.store(pack_h(hv, (unsigned)(step + 1)), cuda::memory_order_relaxed);
        }
    }

    // ---- outputs: h and c straight from owner registers ----
    if (t < 16) {
        out[1 + ((c << 4) + t)]   = hv;
        out[513 + ((c << 4) + t)] = cv;
    }

    // ---- CTA 0: final fc once every word carries tag TSTEPS ----
    if (c == 0) {
        float hfin;
        {
            dev_atomic_u64 href(g_hw[TSTEPS & 1][t]);   // TSTEPS even -> buf 0
            u64 word;
            int guard = 0;
            do {
                word = href.load(cuda::memory_order_relaxed);
            } while ((unsigned)(word >> 32) != (unsigned)TSTEPS &&
                     ++guard < SPIN_GUARD);
            hfin = __uint_as_float((unsigned)word);
        }
        float p = hfin * fc_w[t];
        #pragma unroll
        for (int o = 16; o > 0; o >>= 1) p += __shfl_down_sync(0xffffffffu, p, o);
        if ((t & 31) == 0) red[t >> 5] = p;
        __syncthreads();
        if (t == 0) {
            float acc = fc_b[0];
            #pragma unroll
            for (int i = 0; i < 16; ++i) acc += red[i];
            out[0] = sigm(acc);
        }
    }
}

// ================= launch =================
extern "C" void kernel_launch(void* const* d_in, const int* in_sizes, int n_in,
                              void* d_out, int out_size)
{
    const int*   x     = (const int*)  d_in[0];
    const float* h0    = (const float*)d_in[1];
    const float* c0    = (const float*)d_in[2];
    const float* emb   = (const float*)d_in[3];
    const float* W_ih  = (const float*)d_in[4];
    const float* W_hh  = (const float*)d_in[5];
    const float* b_ih  = (const float*)d_in[6];
    const float* b_hh  = (const float*)d_in[7];
    const float* fc_w  = (const float*)d_in[8];
    const float* fc_b  = (const float*)d_in[9];
    float* out = (float*)d_out;

    dim3 pgrid(G4 / 16, (TSTEPS + 15) / 16);   // 128 x 19
    pre_kernel<<<pgrid, 256>>>(x, emb, W_ih, b_ih, b_hh, h0);
    lstm_persist<<<NCTA, TPB>>>(W_hh, c0, fc_w, fc_b, out);
}

// round 10
// speedup vs baseline: 4.2124x; 4.2124x over previous
#include <cuda_runtime.h>
#include <cuda/atomic>
#include <cstdint>

#define TSTEPS 300
#define HIDN   512
#define EMBD   300
#define G4     2048      // 4*HIDN
#define NCTA   32
#define TPB    512
#define SPIN_GUARD (1 << 16)
#define HPAD   16        // u64s per hidden unit -> one 128B line each

typedef unsigned long long u64;

// ---------------- scratch (static __device__, no allocs) ----------------
__device__ __align__(16)  float g_pre[TSTEPS * G4];   // input-side gates (+biases)
__device__ __align__(128) u64   g_hw[2][HIDN * HPAD]; // tagged hidden words, one per
                                                      // 128B line: (tag<<32)|bits
using dev_atomic_u64 = cuda::atomic_ref<u64, cuda::thread_scope_device>;

__device__ __forceinline__ u64 pack_h(float v, unsigned tag) {
    return ((u64)tag << 32) | (u64)__float_as_uint(v);
}

__device__ __forceinline__ float sigm(float x) { return 1.f / (1.f + __expf(-x)); }
__device__ __forceinline__ float tanh_f(float x) {
    // overflow-safe: tanh(x) = sign(x) * (1 - 2/(exp(2|x|)+1))
    float e = __expf(2.f * fabsf(x));
    float r = 1.f - 2.f / (e + 1.f);
    return copysignf(r, x);
}

// ================= Phase 1: pre[t][row] = W_ih @ emb[x[t]] + b_ih + b_hh ==========
// grid (128, 19), block 256.  Block covers 16 rows x 16 timesteps; K=300 loop.
__global__ void pre_kernel(const int* __restrict__ x,
                           const float* __restrict__ emb,
                           const float* __restrict__ W_ih,
                           const float* __restrict__ b_ih,
                           const float* __restrict__ b_hh,
                           const float* __restrict__ h0)
{
    __shared__ float E[16][301];   // stride 301 -> conflict-free column reads
    const int tB = blockIdx.y * 16;
    const int rB = blockIdx.x * 16;

    for (int idx = threadIdx.x; idx < 16 * EMBD; idx += 256) {
        int tt = idx / EMBD, k = idx % EMBD;
        int t = tB + tt;
        E[tt][k] = (t < TSTEPS) ? emb[(size_t)x[t] * EMBD + k] : 0.f;
    }
    __syncthreads();

    const int t_local = threadIdx.x & 15;
    const int r_local = threadIdx.x >> 4;
    const int r = rB + r_local;
    const int t = tB + t_local;

    const float* wr = W_ih + (size_t)r * EMBD;
    float a0 = 0.f, a1 = 0.f, a2 = 0.f, a3 = 0.f;
    #pragma unroll 4
    for (int k = 0; k < EMBD; k += 4) {
        a0 = fmaf(wr[k + 0], E[t_local][k + 0], a0);
        a1 = fmaf(wr[k + 1], E[t_local][k + 1], a1);
        a2 = fmaf(wr[k + 2], E[t_local][k + 2], a2);
        a3 = fmaf(wr[k + 3], E[t_local][k + 3], a3);
    }
    if (t < TSTEPS)
        g_pre[(size_t)t * G4 + r] = (a0 + a1) + (a2 + a3) + b_ih[r] + b_hh[r];

    // block (0,0): seed h words with tag 0 and poison the other buffer's tags
    // (kills any cross-replay tag collision)
    if (blockIdx.x == 0 && blockIdx.y == 0) {
        for (int i = threadIdx.x; i < HIDN; i += 256) {
            dev_atomic_u64 a0ref(g_hw[0][i * HPAD]);
            dev_atomic_u64 a1ref(g_hw[1][i * HPAD]);
            a0ref.store(pack_h(h0[i], 0u), cuda::memory_order_relaxed);
            a1ref.store(((u64)0xFFFFFFFFu << 32), cuda::memory_order_relaxed);
        }
    }
}

// ================= Phase 2: persistent recurrence, tagged-word sync =================
// 32 CTAs x 512 threads.  CTA c owns hidden units [16c,16c+16) -> 64 gate rows.
// Thread t: row rr = t>>3 (gate = rr>>4, unit = rr&15), h-chunk s = t&7 (64 MACs).
// W_hh slice lives in registers for all 300 steps.
// Sync: each h word carries its step tag; consumers poll their own word until
// tag == step (payload + signal share one atomic 64-bit word -> relaxed ordering,
// no fences).  Each word sits on its OWN 128B line so ~16K chip-wide pollers
// spread over 512 lines instead of 32 (kills LTS hot-line queueing).
// Activations are applied by the 64 s==0 reducer threads (parallel MUFU);
// owners only combine 4 activated gates, update c, tanh, publish.
__global__ void __launch_bounds__(TPB, 1)
lstm_persist(const float* __restrict__ W_hh,
             const float* __restrict__ c0,
             const float* __restrict__ fc_w,
             const float* __restrict__ fc_b,
             float* __restrict__ out)
{
    const int c  = blockIdx.x;
    const int t  = threadIdx.x;
    const int rr = t >> 3;                 // 0..63
    const int s  = t & 7;                  // 0..7
    const int gate = rr >> 4;              // 0..3 (i,f,g,o)
    const int unit = (c << 4) + (rr & 15); // global hidden unit
    const int grow = gate * HIDN + unit;   // global gate row

    __shared__ __align__(16) float hs[8 * 68];  // 8 segments x 64 h-values, stride 68
    __shared__ float gsm[64];              // activated gates per row
    __shared__ float red[16];

    // ---- load W_hh slice into registers (kept for all 300 steps) ----
    float w[64];
    {
        const float4* wrow =
            reinterpret_cast<const float4*>(W_hh + (size_t)grow * HIDN + s * 64);
        #pragma unroll
        for (int i = 0; i < 16; ++i) {
            float4 v = wrow[i];
            w[4 * i + 0] = v.x; w[4 * i + 1] = v.y;
            w[4 * i + 2] = v.z; w[4 * i + 3] = v.w;
        }
    }

    float cv = 0.f, hv = 0.f;              // state for the 16 owner threads
    if (t < 16) cv = c0[(c << 4) + t];

    for (int step = 0; step < TSTEPS; ++step) {
        const int buf = step & 1;
        const unsigned utag = (unsigned)step;

        // independent of h: issue the input-side gate fetch before the poll so
        // it is in flight during the spin (only s==0 threads need it)
        float prev = 0.f;
        if (s == 0) prev = __ldg(&g_pre[(size_t)step * G4 + grow]);

        // ---- poll own tagged word (own 128B line) until tag == step ----
        {
            dev_atomic_u64 href(g_hw[buf][t * HPAD]);
            u64 word;
            int guard = 0;
            do {
                word = href.load(cuda::memory_order_relaxed);
            } while ((unsigned)(word >> 32) != utag && ++guard < SPIN_GUARD);
            hs[(t >> 6) * 68 + (t & 63)] = __uint_as_float((unsigned)word);
        }
        __syncthreads();                          // stage -> read

        // ---- 64-MAC partial dot: W in regs, h from conflict-free smem ----
        float a0 = 0.f, a1 = 0.f, a2 = 0.f, a3 = 0.f;
        const float4* hp4 = reinterpret_cast<const float4*>(&hs[s * 68]);
        #pragma unroll
        for (int i = 0; i < 16; ++i) {
            float4 h4 = hp4[i];
            a0 = fmaf(w[4 * i + 0], h4.x, a0);
            a1 = fmaf(w[4 * i + 1], h4.y, a1);
            a2 = fmaf(w[4 * i + 2], h4.z, a2);
            a3 = fmaf(w[4 * i + 3], h4.w, a3);
        }
        float part = (a0 + a1) + (a2 + a3);
        part += __shfl_down_sync(0xffffffffu, part, 4, 8);
        part += __shfl_down_sync(0xffffffffu, part, 2, 8);
        part += __shfl_down_sync(0xffffffffu, part, 1, 8);

        // ---- s==0 thread of each row: add pre and apply the gate activation ----
        if (s == 0) {
            float gsum = part + prev;
            // rows 0..15 i(sigm), 16..31 f(sigm), 32..47 g(tanh), 48..63 o(sigm)
            gsm[rr] = (rr < 32) ? sigm(gsum)
                                : ((rr < 48) ? tanh_f(gsum) : sigm(gsum));
        }
        __syncthreads();                          // gsm write -> read; hs reads done

        // ---- owners (t<16): combine 4 activated gates, update state, publish ----
        if (t < 16) {
            float i_ = gsm[t];
            float f_ = gsm[16 + t];
            float g_ = gsm[32 + t];
            float o_ = gsm[48 + t];
            float cn = fmaf(f_, cv, i_ * g_);
            cv = cn;
            hv = o_ * tanh_f(cn);
            dev_atomic_u64 hdst(g_hw[buf ^ 1][((c << 4) + t) * HPAD]);
            hdst.store(pack_h(hv, (unsigned)(step + 1)), cuda::memory_order_relaxed);
        }
        // no trailing sync: next iteration's hs writes are gated by the per-thread
        // poll, and the gsm rewrite is gated by the next first sync
    }

    // ---- outputs: h and c straight from owner registers ----
    if (t < 16) {
        out[1 + ((c << 4) + t)]   = hv;
        out[513 + ((c << 4) + t)] = cv;
    }

    // ---- CTA 0: final fc once every word carries tag TSTEPS ----
    if (c == 0) {
        float hfin;
        {
            dev_atomic_u64 href(g_hw[TSTEPS & 1][t * HPAD]);  // TSTEPS even -> buf 0
            u64 word;
            int guard = 0;
            do {
                word = href.load(cuda::memory_order_relaxed);
            } while ((unsigned)(word >> 32) != (unsigned)TSTEPS &&
                     ++guard < SPIN_GUARD);
            hfin = __uint_as_float((unsigned)word);
        }
        float p = hfin * fc_w[t];
        #pragma unroll
        for (int o = 16; o > 0; o >>= 1) p += __shfl_down_sync(0xffffffffu, p, o);
        if ((t & 31) == 0) red[t >> 5] = p;
        __syncthreads();
        if (t == 0) {
            float acc = fc_b[0];
            #pragma unroll
            for (int i = 0; i < 16; ++i) acc += red[i];
            out[0] = sigm(acc);
        }
    }
}

// ================= launch =================
extern "C" void kernel_launch(void* const* d_in, const int* in_sizes, int n_in,
                              void* d_out, int out_size)
{
    const int*   x     = (const int*)  d_in[0];
    const float* h0    = (const float*)d_in[1];
    const float* c0    = (const float*)d_in[2];
    const float* emb   = (const float*)d_in[3];
    const float* W_ih  = (const float*)d_in[4];
    const float* W_hh  = (const float*)d_in[5];
    const float* b_ih  = (const float*)d_in[6];
    const float* b_hh  = (const float*)d_in[7];
    const float* fc_w  = (const float*)d_in[8];
    const float* fc_b  = (const float*)d_in[9];
    float* out = (float*)d_out;

    dim3 pgrid(G4 / 16, (TSTEPS + 15) / 16);   // 128 x 19
    pre_kernel<<<pgrid, 256>>>(x, emb, W_ih, b_ih, b_hh, h0);
    lstm_persist<<<NCTA, TPB>>>(W_hh, c0, fc_w, fc_b, out);
}

// round 11
// speedup vs baseline: 4.9423x; 1.1733x over previous
#include <cuda_runtime.h>
#include <cuda/atomic>
#include <cstdint>

#define TSTEPS 300
#define HIDN   512
#define EMBD   300
#define G4     2048      // 4*HIDN
#define NCTA   32
#define TPB    512
#define SPIN_GUARD (1 << 16)

typedef unsigned long long u64;

// ---------------- scratch (static __device__, no allocs) ----------------
__device__ __align__(16) float g_pre[TSTEPS * G4]; // input-side gates (+biases)
__device__ __align__(16) u64   g_hw[2][HIDN];      // tagged hidden words: (tag<<32)|bits
                                                   // tag s = "h after s steps"

using dev_atomic_u64 = cuda::atomic_ref<u64, cuda::thread_scope_device>;

__device__ __forceinline__ u64 pack_h(float v, unsigned tag) {
    return ((u64)tag << 32) | (u64)__float_as_uint(v);
}

__device__ __forceinline__ float sigm(float x) { return 1.f / (1.f + __expf(-x)); }
__device__ __forceinline__ float tanh_f(float x) {
    // overflow-safe: tanh(x) = sign(x) * (1 - 2/(exp(2|x|)+1))
    float e = __expf(2.f * fabsf(x));
    float r = 1.f - 2.f / (e + 1.f);
    return copysignf(r, x);
}

// ================= Phase 1: pre[t][row] = W_ih @ emb[x[t]] + b_ih + b_hh ==========
// grid (128, 19), block 256.  Block covers 16 rows x 16 timesteps; K=300 loop.
__global__ void pre_kernel(const int* __restrict__ x,
                           const float* __restrict__ emb,
                           const float* __restrict__ W_ih,
                           const float* __restrict__ b_ih,
                           const float* __restrict__ b_hh,
                           const float* __restrict__ h0)
{
    __shared__ float E[16][301];   // stride 301 -> conflict-free column reads
    const int tB = blockIdx.y * 16;
    const int rB = blockIdx.x * 16;

    for (int idx = threadIdx.x; idx < 16 * EMBD; idx += 256) {
        int tt = idx / EMBD, k = idx % EMBD;
        int t = tB + tt;
        E[tt][k] = (t < TSTEPS) ? emb[(size_t)x[t] * EMBD + k] : 0.f;
    }
    __syncthreads();

    const int t_local = threadIdx.x & 15;
    const int r_local = threadIdx.x >> 4;
    const int r = rB + r_local;
    const int t = tB + t_local;

    const float* wr = W_ih + (size_t)r * EMBD;
    float a0 = 0.f, a1 = 0.f, a2 = 0.f, a3 = 0.f;
    #pragma unroll 4
    for (int k = 0; k < EMBD; k += 4) {
        a0 = fmaf(wr[k + 0], E[t_local][k + 0], a0);
        a1 = fmaf(wr[k + 1], E[t_local][k + 1], a1);
        a2 = fmaf(wr[k + 2], E[t_local][k + 2], a2);
        a3 = fmaf(wr[k + 3], E[t_local][k + 3], a3);
    }
    if (t < TSTEPS)
        g_pre[(size_t)t * G4 + r] = (a0 + a1) + (a2 + a3) + b_ih[r] + b_hh[r];

    // block (0,0): seed h words with tag 0 and poison the other buffer's tags
    // (kills any cross-replay tag collision)
    if (blockIdx.x == 0 && blockIdx.y == 0) {
        for (int i = threadIdx.x; i < HIDN; i += 256) {
            dev_atomic_u64 a0ref(g_hw[0][i]);
            dev_atomic_u64 a1ref(g_hw[1][i]);
            a0ref.store(pack_h(h0[i], 0u), cuda::memory_order_relaxed);
            a1ref.store(((u64)0xFFFFFFFFu << 32), cuda::memory_order_relaxed);
        }
    }
}

// ================= Phase 2: persistent recurrence, single-bar hybrid =============
// 32 CTAs x 512 threads.  CTA c owns hidden units [16c,16c+16) -> 64 gate rows.
// Warp-pair p (warps 2p,2p+1) handles all 64 rows x cols [64p, 64p+64).
// Thread (pair p, half, lane): row q = half*32+lane (gate = q>>4, unit = q&15);
// W_hh[grow(q)][64p..64p+64) in 64 registers.  Each lane polls TWO tagged L2
// h-words (units 64p+lane, 64p+32+lane); the 64 h values are shfl-broadcast
// during the FMA loop (no smem staging, no first barrier).
// Partials -> s_part[parity][chunk][row] (parity double-buffer: without a second
// bar a pair warp can run ONE step ahead of its own CTA's owners; bar(s+1)
// gates any step-s slot overwrite at s+2 behind the owners' step-s reads).
// ONE __syncthreads per step; owners gather 8 partials x 4 gates, apply all
// activations, update c, publish tagged h.  Publishes stay bar-gated, which is
// what makes the single-intermediate g_hw overwrite safe (R7 proof).
__global__ void __launch_bounds__(TPB, 1)
lstm_persist(const float* __restrict__ W_hh,
             const float* __restrict__ c0,
             const float* __restrict__ fc_w,
             const float* __restrict__ fc_b,
             float* __restrict__ out)
{
    const int c    = blockIdx.x;
    const int t    = threadIdx.x;
    const int warp = t >> 5;
    const int lane = t & 31;
    const int pair = warp >> 1;            // 0..7  (column chunk)
    const int half = warp & 1;             // 0/1
    const int q    = (half << 5) | lane;   // row in CTA, 0..63
    const int grow = (q >> 4) * HIDN + (c << 4) + (q & 15);  // global gate row

    const int unitA = (pair << 6) + lane;        // first polled unit
    const int unitB = (pair << 6) + 32 + lane;   // second polled unit

    __shared__ float s_part[2][8][64];     // [parity][chunk][row] partials
    __shared__ float red[16];

    // ---- load W_hh slice into registers (kept for all 300 steps) ----
    float w[64];
    {
        const float4* wrow =
            reinterpret_cast<const float4*>(W_hh + (size_t)grow * HIDN + (pair << 6));
        #pragma unroll
        for (int i = 0; i < 16; ++i) {
            float4 v = wrow[i];
            w[4 * i + 0] = v.x; w[4 * i + 1] = v.y;
            w[4 * i + 2] = v.z; w[4 * i + 3] = v.w;
        }
    }

    float cv = 0.f, hv = 0.f;              // state for the 16 owner threads
    if (t < 16) cv = c0[(c << 4) + t];

    for (int step = 0; step < TSTEPS; ++step) {
        const int buf = step & 1;          // h-buffer parity AND s_part parity
        const unsigned utag = (unsigned)step;

        // owners prefetch their 4 input-side gate values (in flight during poll)
        float p0 = 0.f, p1 = 0.f, p2 = 0.f, p3 = 0.f;
        if (t < 16) {
            const float* pb = g_pre + (size_t)step * G4 + (c << 4) + t;
            p0 = __ldg(pb);
            p1 = __ldg(pb + HIDN);
            p2 = __ldg(pb + 2 * HIDN);
            p3 = __ldg(pb + 3 * HIDN);
        }

        // ---- poll the two tagged L2 words until both carry tag == step ----
        float vA, vB;
        {
            dev_atomic_u64 ra(g_hw[buf][unitA]);
            dev_atomic_u64 rb(g_hw[buf][unitB]);
            u64 a, b;
            int guard = 0;
            do {
                a = ra.load(cuda::memory_order_relaxed);
                b = rb.load(cuda::memory_order_relaxed);
            } while (((unsigned)(a >> 32) != utag || (unsigned)(b >> 32) != utag) &&
                     ++guard < SPIN_GUARD);
            vA = __uint_as_float((unsigned)a);
            vB = __uint_as_float((unsigned)b);
        }

        // ---- 64-MAC dot via shfl broadcast (no smem staging) ----
        float a0 = 0.f, a1 = 0.f, a2 = 0.f, a3 = 0.f;
        #pragma unroll
        for (int k = 0; k < 32; k += 4) {
            a0 = fmaf(w[k + 0], __shfl_sync(0xffffffffu, vA, k + 0), a0);
            a1 = fmaf(w[k + 1], __shfl_sync(0xffffffffu, vA, k + 1), a1);
            a2 = fmaf(w[k + 2], __shfl_sync(0xffffffffu, vA, k + 2), a2);
            a3 = fmaf(w[k + 3], __shfl_sync(0xffffffffu, vA, k + 3), a3);
        }
        #pragma unroll
        for (int k = 0; k < 32; k += 4) {
            a0 = fmaf(w[32 + k + 0], __shfl_sync(0xffffffffu, vB, k + 0), a0);
            a1 = fmaf(w[32 + k + 1], __shfl_sync(0xffffffffu, vB, k + 1), a1);
            a2 = fmaf(w[32 + k + 2], __shfl_sync(0xffffffffu, vB, k + 2), a2);
            a3 = fmaf(w[32 + k + 3], __shfl_sync(0xffffffffu, vB, k + 3), a3);
        }
        s_part[buf][pair][q] = (a0 + a1) + (a2 + a3);

        __syncthreads();                   // the ONLY barrier in the step

        // ---- owners (t<16): gather 8x4 partials, activate, update, publish ----
        if (t < 16) {
            float gs[4];
            #pragma unroll
            for (int g = 0; g < 4; ++g) {
                const int q2 = (g << 4) + t;
                float s01 = (s_part[buf][0][q2] + s_part[buf][1][q2]) +
                            (s_part[buf][2][q2] + s_part[buf][3][q2]);
                float s23 = (s_part[buf][4][q2] + s_part[buf][5][q2]) +
                            (s_part[buf][6][q2] + s_part[buf][7][q2]);
                gs[g] = s01 + s23;
            }
            float i_ = sigm(gs[0] + p0);
            float f_ = sigm(gs[1] + p1);
            float g_ = tanh_f(gs[2] + p2);
            float o_ = sigm(gs[3] + p3);
            float cn = fmaf(f_, cv, i_ * g_);
            cv = cn;
            hv = o_ * tanh_f(cn);
            dev_atomic_u64 hdst(g_hw[buf ^ 1][(c << 4) + t]);
            hdst.store(pack_h(hv, (unsigned)(step + 1)), cuda::memory_order_relaxed);
        }
        // no trailing sync: s_part slot reuse is two steps away (parity), and the
        // bar above gates it behind the owners' reads (see header comment)
    }

    // ---- outputs: h and c straight from owner registers ----
    if (t < 16) {
        out[1 + ((c << 4) + t)]   = hv;
        out[513 + ((c << 4) + t)] = cv;
    }

    // ---- CTA 0: final fc once every word carries tag TSTEPS ----
    if (c == 0) {
        float hfin;
        {
            dev_atomic_u64 href(g_hw[TSTEPS & 1][t]);   // TSTEPS even -> buf 0
            u64 word;
            int guard = 0;
            do {
                word = href.load(cuda::memory_order_relaxed);
            } while ((unsigned)(word >> 32) != (unsigned)TSTEPS &&
                     ++guard < SPIN_GUARD);
            hfin = __uint_as_float((unsigned)word);
        }
        float p = hfin * fc_w[t];
        #pragma unroll
        for (int o = 16; o > 0; o >>= 1) p += __shfl_down_sync(0xffffffffu, p, o);
        if ((t & 31) == 0) red[t >> 5] = p;
        __syncthreads();
        if (t == 0) {
            float acc = fc_b[0];
            #pragma unroll
            for (int i = 0; i < 16; ++i) acc += red[i];
            out[0] = sigm(acc);
        }
    }
}

// ================= launch =================
extern "C" void kernel_launch(void* const* d_in, const int* in_sizes, int n_in,
                              void* d_out, int out_size)
{
    const int*   x     = (const int*)  d_in[0];
    const float* h0    = (const float*)d_in[1];
    const float* c0    = (const float*)d_in[2];
    const float* emb   = (const float*)d_in[3];
    const float* W_ih  = (const float*)d_in[4];
    const float* W_hh  = (const float*)d_in[5];
    const float* b_ih  = (const float*)d_in[6];
    const float* b_hh  = (const float*)d_in[7];
    const float* fc_w  = (const float*)d_in[8];
    const float* fc_b  = (const float*)d_in[9];
    float* out = (float*)d_out;

    dim3 pgrid(G4 / 16, (TSTEPS + 15) / 16);   // 128 x 19
    pre_kernel<<<pgrid, 256>>>(x, emb, W_ih, b_ih, b_hh, h0);
    lstm_persist<<<NCTA, TPB>>>(W_hh, c0, fc_w, fc_b, out);
}